// round 2
// baseline (speedup 1.0000x reference)
#include <cuda_runtime.h>
#include <cuda_bf16.h>

// Problem: B=2, C=4, D=64, H=256, W=256
#define HW    65536        // H*W
#define DHW   4194304      // D*H*W
#define NELEM 25165824.0   // B*(C-1)*DHW

// Tile: TH=16 rows, TW=64 cols, D split in 2 chunks of 32 -> 2*16*4*2 = 256 blocks
#define TH 16
#define TW 64
#define SH 18              // TH + 2 halo
#define SW 72              // 4 + TW + 4 pad (interior starts at +4, float4 aligned)
#define NHALO 1188         // SH * 66 actually-loaded halo voxels per plane

__device__ double g_acc;

__global__ void zero_acc_kernel() { g_acc = 0.0; }

__device__ __forceinline__ float f4get(const float4& f, int j) {
    switch (j) { case 0: return f.x; case 1: return f.y; case 2: return f.z; default: return f.w; }
}
__device__ __forceinline__ int i4get(const int4& f, int j) {
    switch (j) { case 0: return f.x; case 1: return f.y; case 2: return f.z; default: return f.w; }
}

__global__ void __launch_bounds__(256, 2)
fused_kernel(const float* __restrict__ logits, const int* __restrict__ targets) {
    // ring of 3 z-planes of softmax probs (3 fg classes), with h/w halo
    __shared__ float sp[3][3][SH][SW];   // 46.7 KB

    int q  = blockIdx.x;
    int wb = q & 3;  q >>= 2;   // W/TW = 4
    int hb = q & 15; q >>= 4;   // H/TH = 16
    int dc = q & 1;  q >>= 1;   // D chunks = 2
    int b  = q;                 // B = 2
    int h0 = hb * TH, w0 = wb * TW, dlo = dc * 32;
    int tid = threadIdx.x;

    const float* Lb = logits  + (size_t)b * 4 * DHW;
    const int*   Tb = targets + (size_t)b * DHW;

    float acc = 0.f;

    for (int step = 0; step < 34; ++step) {
        int dload = dlo - 1 + step;          // plane to produce: dlo-1 .. dlo+32
        int slot  = step % 3;
        bool dvalid = (dload >= 0) && (dload <= 63);

        // ---- softmax producer: fill plane `dload` (zeros if out of volume) ----
        float xs[5][4];
        short hhv[5], wwv[5];
        bool  val[5];
#pragma unroll
        for (int it = 0; it < 5; ++it) {
            int idx = tid + it * 256;
            int hh = idx / 66;
            int ww = idx - hh * 66;
            int h = h0 + hh - 1, w = w0 + ww - 1;
            bool v = (idx < NHALO) && dvalid &&
                     (h >= 0) && (h < 256) && (w >= 0) && (w < 256);
            val[it] = v; hhv[it] = (short)hh; wwv[it] = (short)ww;
            const float* p = Lb + (size_t)dload * HW + h * 256 + w;
            xs[it][0] = v ? __ldg(p)           : 0.f;
            xs[it][1] = v ? __ldg(p + DHW)     : 0.f;
            xs[it][2] = v ? __ldg(p + 2 * DHW) : 0.f;
            xs[it][3] = v ? __ldg(p + 3 * DHW) : 0.f;
        }
#pragma unroll
        for (int it = 0; it < 5; ++it) {
            int idx = tid + it * 256;
            if (idx < NHALO) {
                float p1 = 0.f, p2 = 0.f, p3 = 0.f;
                if (val[it]) {
                    float a = xs[it][0], x1 = xs[it][1], x2 = xs[it][2], x3 = xs[it][3];
                    float m  = fmaxf(fmaxf(a, x1), fmaxf(x2, x3));
                    float e0 = __expf(a - m),  e1 = __expf(x1 - m);
                    float e2 = __expf(x2 - m), e3 = __expf(x3 - m);
                    float inv = __frcp_rn(e0 + e1 + e2 + e3);
                    p1 = e1 * inv; p2 = e2 * inv; p3 = e3 * inv;
                }
                int hh = hhv[it], ww = wwv[it] + 3;   // halo col 0 -> smem col 3
                sp[slot][0][hh][ww] = p1;
                sp[slot][1][hh][ww] = p2;
                sp[slot][2][hh][ww] = p3;
            }
        }
        __syncthreads();

        // ---- consumer: output plane dout = dlo + step - 2 ----
        if (step >= 2) {
            int dout = dlo + step - 2;
            int s0 = (step - 2) % 3;   // plane dout-1
            int s1 = (step - 1) % 3;   // plane dout
            int s2 = slot;             // plane dout+1
            int row = tid >> 4, wl = (tid & 15) << 2;
            int h = h0 + row, wg = w0 + wl;
            int hh = row + 1, ww = wl + 4;

            const int* tp = Tb + (size_t)dout * HW + h * 256 + wg;
            const int4 zi = make_int4(0, 0, 0, 0);
            int4 tc  = *(const int4*)tp;
            int4 tdm = (dout > 0)  ? *(const int4*)(tp - HW)  : zi;
            int4 tdp = (dout < 63) ? *(const int4*)(tp + HW)  : zi;
            int4 thm = (h > 0)     ? *(const int4*)(tp - 256) : zi;
            int4 thp = (h < 255)   ? *(const int4*)(tp + 256) : zi;
            int  tl  = (wg > 0)    ? tp[-1] : 0;
            int  tr  = (wg < 252)  ? tp[4]  : 0;

#pragma unroll
            for (int c = 0; c < 3; ++c) {
                float4 c4 = *(const float4*)&sp[s1][c][hh][ww];
                float4 u4 = *(const float4*)&sp[s1][c][hh - 1][ww];
                float4 d4 = *(const float4*)&sp[s1][c][hh + 1][ww];
                float4 fr = *(const float4*)&sp[s0][c][hh][ww];
                float4 bk = *(const float4*)&sp[s2][c][hh][ww];
                float  lf = sp[s1][c][hh][ww - 1];
                float  rt = sp[s1][c][hh][ww + 4];
                int c1 = c + 1;
#pragma unroll
                for (int j = 0; j < 4; ++j) {
                    float pl = (j == 0) ? lf : f4get(c4, j - 1);
                    float pr = (j == 3) ? rt : f4get(c4, j + 1);
                    float lap = f4get(u4, j) + f4get(d4, j) + f4get(fr, j)
                              + f4get(bk, j) + pl + pr - 6.f * f4get(c4, j);
                    int tcj = i4get(tc, j);
                    int tlj = (j == 0) ? tl : i4get(tc, j - 1);
                    int trj = (j == 3) ? tr : i4get(tc, j + 1);
                    int cnt = (i4get(tdm, j) == c1) + (i4get(tdp, j) == c1)
                            + (i4get(thm, j) == c1) + (i4get(thp, j) == c1)
                            + (tlj == c1) + (trj == c1);
                    float lapt = (float)(cnt - 6 * (tcj == c1));
                    float diff = fabsf(lap) - fabsf(lapt);
                    acc = fmaf(diff, diff, acc);
                }
            }
        }
        __syncthreads();
    }

    // ---- block reduction -> double atomic ----
#pragma unroll
    for (int o = 16; o; o >>= 1) acc += __shfl_down_sync(0xffffffffu, acc, o);
    __shared__ float ws[8];
    int lane = tid & 31, wid = tid >> 5;
    if (lane == 0) ws[wid] = acc;
    __syncthreads();
    if (wid == 0) {
        acc = (lane < 8) ? ws[lane] : 0.f;
#pragma unroll
        for (int o = 4; o; o >>= 1) acc += __shfl_down_sync(0xffffffffu, acc, o);
        if (lane == 0) atomicAdd(&g_acc, (double)acc);
    }
}

__global__ void finalize_kernel(float* __restrict__ out) {
    out[0] = (float)(g_acc * (1.0 / NELEM));
}

extern "C" void kernel_launch(void* const* d_in, const int* in_sizes, int n_in,
                              void* d_out, int out_size) {
    const float* logits  = (const float*)d_in[0];
    const int*   targets = (const int*)d_in[1];
    float* out = (float*)d_out;

    zero_acc_kernel<<<1, 1>>>();
    fused_kernel<<<256, 256>>>(logits, targets);
    finalize_kernel<<<1, 1>>>(out);
}